// round 1
// baseline (speedup 1.0000x reference)
#include <cuda_runtime.h>
#include <cstdint>

typedef unsigned long long u64;

#define Bn   16
#define R    360
#define RPAD 384   // padded row length (float2 units) for u/v scratch

// Scratch: u2[b][dpair k][i] = (u[i][2k], u[i][2k+1]) packed fp32x2; same for v (v includes +b_out)
__device__ u64 g_u2[Bn * 32 * RPAD];
__device__ u64 g_v2[Bn * 32 * RPAD];

// ---------- packed fp32x2 helpers (sm_100+) ----------
__device__ __forceinline__ u64 pack2(float x, float y) {
    u64 d; asm("mov.b64 %0, {%1, %2};" : "=l"(d) : "f"(x), "f"(y)); return d;
}
__device__ __forceinline__ void unpack2(u64 a, float &x, float &y) {
    asm("mov.b64 {%0, %1}, %2;" : "=f"(x), "=f"(y) : "l"(a));
}
__device__ __forceinline__ u64 fadd2(u64 a, u64 b) {
    u64 d; asm("add.rn.f32x2 %0, %1, %2;" : "=l"(d) : "l"(a), "l"(b)); return d;
}
__device__ __forceinline__ void ffma2(u64 &d, u64 a, u64 b) {
    asm("fma.rn.f32x2 %0, %1, %2, %0;" : "+l"(d) : "l"(a), "l"(b));
}
__device__ __forceinline__ u64 relu2(u64 a) {
    float lo, hi; unpack2(a, lo, hi);
    lo = fmaxf(lo, 0.0f); hi = fmaxf(hi, 0.0f);
    return pack2(lo, hi);
}

// ============================================================================
// Kernel 1: u = x @ Wout[0:64], v = x @ Wout[64:128] + b_out
// Treated as one GEMM: [5760 x 64] @ [64 x 128], fp32x2-packed over k-pairs.
// Stores transposed: g_u2[b][k][i] = (u[i][2k], u[i][2k+1]).
// ============================================================================
__global__ __launch_bounds__(256, 2) void k1_uv(
    const float* __restrict__ x,      // [5760][64]
    const float* __restrict__ Wout,   // [128][64]
    const float* __restrict__ bout)   // [64]
{
    __shared__ u64 xs[32][64];   // [kpair][row]  (x[row][2p], x[row][2p+1])
    __shared__ u64 Wu[32][64];   // [kpair][d]    (Wout[2p][d],    Wout[2p+1][d])
    __shared__ u64 Wv[32][64];   // [kpair][d]    (Wout[64+2p][d], Wout[64+2p+1][d])

    const int t = threadIdx.x;
    const int row0 = blockIdx.x * 64;

    // Fill xs (i-major: conflict-free smem stores; global reads are scattered but x is tiny)
    {
        const u64* x2 = (const u64*)x;   // float2 view of x rows (32 per row)
        const int i = t & 63, p0 = t >> 6;
        #pragma unroll
        for (int p = p0; p < 32; p += 4)
            xs[p][i] = x2[(row0 + i) * 32 + p];
    }
    // Fill Wu / Wv (coalesced on d)
    {
        const int c = t & 63, p0 = t >> 6;
        #pragma unroll
        for (int p = p0; p < 32; p += 4) {
            Wu[p][c] = pack2(Wout[(2 * p) * 64 + c],      Wout[(2 * p + 1) * 64 + c]);
            Wv[p][c] = pack2(Wout[(64 + 2 * p) * 64 + c], Wout[(65 + 2 * p) * 64 + c]);
        }
    }
    __syncthreads();

    // Thread tile: 4 rows (stride-16 interleaved) x 8 cols
    const int rt = t & 15;            // row lane: rows rt + 16*ii
    const int ct = t >> 4;            // 0..15 -> 8 cols each; ct<8 => u cols, ct>=8 => v cols
    const int ccol = (ct & 7) * 8;    // d-base within selected half
    const bool isv = (ct >= 8);
    const u64 (*Ws)[64] = isv ? Wv : Wu;

    u64 acc[4][8];
    #pragma unroll
    for (int ii = 0; ii < 4; ii++)
        #pragma unroll
        for (int j = 0; j < 8; j++) acc[ii][j] = 0ull;

    #pragma unroll 8
    for (int p = 0; p < 32; p++) {
        u64 xv[4];
        #pragma unroll
        for (int ii = 0; ii < 4; ii++) xv[ii] = xs[p][rt + 16 * ii];
        u64 wv[8];
        #pragma unroll
        for (int q = 0; q < 4; q++) {
            ulonglong2 w2 = *(const ulonglong2*)&Ws[p][ccol + 2 * q];
            wv[2 * q] = w2.x; wv[2 * q + 1] = w2.y;
        }
        #pragma unroll
        for (int ii = 0; ii < 4; ii++)
            #pragma unroll
            for (int j = 0; j < 8; j++)
                ffma2(acc[ii][j], xv[ii], wv[j]);   // lo: even-k partial, hi: odd-k partial
    }

    // Epilogue: reduce lo+hi, add b_out for v-half, store transposed pairs
    u64* gdst = isv ? g_v2 : g_u2;
    #pragma unroll
    for (int ii = 0; ii < 4; ii++) {
        const int grow = row0 + rt + 16 * ii;     // global row in [0, 5760)
        const int bb = grow / 360;
        const int i = grow - bb * 360;
        #pragma unroll
        for (int j = 0; j < 8; j += 2) {
            float l0, h0, l1, h1;
            unpack2(acc[ii][j], l0, h0);
            unpack2(acc[ii][j + 1], l1, h1);
            float v0 = l0 + h0, v1 = l1 + h1;
            const int dd = ccol + j;
            if (isv) { v0 += __ldg(&bout[dd]); v1 += __ldg(&bout[dd + 1]); }
            gdst[(bb * 32 + (dd >> 1)) * RPAD + i] = pack2(v0, v1);
        }
    }
}

// ============================================================================
// Kernel 2: out[b,rec,send] = relu( sum_d Wcat[d]*relu(u[send,d]+v[rec,d]) + b_cat )
// Tile: 128 rec x 64 send per block, 256 threads, 8x4 outputs/thread,
// fp32x2-packed over d-pairs (FADD2 + 2x FMNMX + FFMA2 per 2 d's).
// ============================================================================
__global__ __launch_bounds__(256, 2) void k2_pair(
    const float* __restrict__ Wcat,   // [64]
    const float* __restrict__ bcat,   // [1]
    float* __restrict__ out)          // [16*360*360]
{
    __shared__ u64 Us[32][64];    // [dpair][send]
    __shared__ u64 Vs[32][128];   // [dpair][rec]

    const int t = threadIdx.x;
    const int b  = blockIdx.z;
    const int s0 = blockIdx.x * 64;
    const int r0 = blockIdx.y * 128;

    // Fill tiles (coalesced global reads, conflict-free smem stores — no transpose needed)
    {
        const int s = t & 63, k0 = t >> 6;
        const u64* gu = g_u2 + b * 32 * RPAD + s0 + s;
        #pragma unroll
        for (int k = k0; k < 32; k += 4) Us[k][s] = gu[k * RPAD];

        const int r = t & 127, kv = t >> 7;
        const u64* gv = g_v2 + b * 32 * RPAD + r0 + r;
        #pragma unroll
        for (int k = kv; k < 32; k += 2) Vs[k][r] = gv[k * RPAD];
    }
    __syncthreads();

    const int sx = t & 15;   // send base 4*sx
    const int ry = t >> 4;   // rec  base 8*ry

    u64 acc[8][4];
    #pragma unroll
    for (int i = 0; i < 8; i++)
        #pragma unroll
        for (int j = 0; j < 4; j++) acc[i][j] = 0ull;

    const u64* w2p = (const u64*)Wcat;

    #pragma unroll 8
    for (int k = 0; k < 32; k++) {
        const u64 w2 = __ldg(&w2p[k]);   // (w[2k], w[2k+1]) — uniform, L1-resident
        u64 uu[4];
        {
            ulonglong2 ua = *(const ulonglong2*)&Us[k][4 * sx];
            ulonglong2 ub = *(const ulonglong2*)&Us[k][4 * sx + 2];
            uu[0] = ua.x; uu[1] = ua.y; uu[2] = ub.x; uu[3] = ub.y;
        }
        u64 vv[8];
        #pragma unroll
        for (int q = 0; q < 4; q++) {
            ulonglong2 va = *(const ulonglong2*)&Vs[k][8 * ry + 2 * q];
            vv[2 * q] = va.x; vv[2 * q + 1] = va.y;
        }
        #pragma unroll
        for (int i = 0; i < 8; i++)
            #pragma unroll
            for (int j = 0; j < 4; j++) {
                u64 tt = relu2(fadd2(uu[j], vv[i]));
                ffma2(acc[i][j], tt, w2);
            }
    }

    // Epilogue: lo+hi + b_cat, relu, vectorized float4 stores
    const float bc = __ldg(bcat);
    const int s = s0 + 4 * sx;
    if (s < R) {
        #pragma unroll
        for (int i = 0; i < 8; i++) {
            const int rec = r0 + 8 * ry + i;
            if (rec < R) {
                float4 o;
                float lx, hx;
                unpack2(acc[i][0], lx, hx); o.x = fmaxf(lx + hx + bc, 0.0f);
                unpack2(acc[i][1], lx, hx); o.y = fmaxf(lx + hx + bc, 0.0f);
                unpack2(acc[i][2], lx, hx); o.z = fmaxf(lx + hx + bc, 0.0f);
                unpack2(acc[i][3], lx, hx); o.w = fmaxf(lx + hx + bc, 0.0f);
                *(float4*)&out[((size_t)(b * R + rec)) * R + s] = o;
            }
        }
    }
}

extern "C" void kernel_launch(void* const* d_in, const int* in_sizes, int n_in,
                              void* d_out, int out_size) {
    (void)in_sizes; (void)n_in; (void)out_size;
    const float* x    = (const float*)d_in[0];  // (16,360,64)
    const float* Wout = (const float*)d_in[1];  // (128,64)
    const float* bout = (const float*)d_in[2];  // (64)
    const float* Wcat = (const float*)d_in[3];  // (64,1)
    const float* bcat = (const float*)d_in[4];  // (1)
    float* out = (float*)d_out;                 // (16,360,360,1) fp32

    k1_uv<<<90, 256>>>(x, Wout, bout);                    // 5760 rows / 64
    k2_pair<<<dim3(6, 3, 16), 256>>>(Wcat, bcat, out);    // 6 send-tiles x 3 rec-tiles x 16 batch
}

// round 2
// speedup vs baseline: 1.0809x; 1.0809x over previous
#include <cuda_runtime.h>
#include <cstdint>

typedef unsigned long long u64;

#define Bn   16
#define R    360
#define RPAD 384   // padded row length (float2 units) for u/v scratch

// Scratch: u2[b][dpair k][i] = (u[i][2k], u[i][2k+1]) packed fp32x2; same for v (v includes +b_out)
__device__ u64 g_u2[Bn * 32 * RPAD];
__device__ u64 g_v2[Bn * 32 * RPAD];

// ---------- packed fp32x2 helpers (sm_100+) ----------
__device__ __forceinline__ u64 pack2(float x, float y) {
    u64 d; asm("mov.b64 %0, {%1, %2};" : "=l"(d) : "f"(x), "f"(y)); return d;
}
__device__ __forceinline__ void unpack2(u64 a, float &x, float &y) {
    asm("mov.b64 {%0, %1}, %2;" : "=f"(x), "=f"(y) : "l"(a));
}
__device__ __forceinline__ u64 fadd2(u64 a, u64 b) {
    u64 d; asm("add.rn.f32x2 %0, %1, %2;" : "=l"(d) : "l"(a), "l"(b)); return d;
}
__device__ __forceinline__ void ffma2(u64 &d, u64 a, u64 b) {
    asm("fma.rn.f32x2 %0, %1, %2, %0;" : "+l"(d) : "l"(a), "l"(b));
}
__device__ __forceinline__ u64 relu2(u64 a) {
    float lo, hi; unpack2(a, lo, hi);
    lo = fmaxf(lo, 0.0f); hi = fmaxf(hi, 0.0f);
    return pack2(lo, hi);
}

// ============================================================================
// Kernel 1: u = x @ Wout[0:64], v = x @ Wout[64:128] + b_out
// [5760 x 64] @ [64 x 128], fp32x2-packed over k-pairs, 48 rows/block -> 120 blocks.
// Stores transposed: g_u2[b][k][i] = (u[i][2k], u[i][2k+1]).
// ============================================================================
#define K1_ROWS 48

__global__ __launch_bounds__(256, 2) void k1_uv(
    const float* __restrict__ x,      // [5760][64]
    const float* __restrict__ Wout,   // [128][64]
    const float* __restrict__ bout)   // [64]
{
    __shared__ u64 xs[32][K1_ROWS];  // [kpair][row]
    __shared__ u64 Wu[32][64];       // [kpair][d]
    __shared__ u64 Wv[32][64];

    const int t = threadIdx.x;
    const int row0 = blockIdx.x * K1_ROWS;

    // Fill xs
    {
        const u64* x2 = (const u64*)x;   // float2 view (32 per row)
        #pragma unroll
        for (int idx = t; idx < 32 * K1_ROWS; idx += 256) {
            const int p = idx / K1_ROWS;
            const int i = idx - p * K1_ROWS;
            xs[p][i] = x2[(row0 + i) * 32 + p];
        }
    }
    // Fill Wu / Wv (coalesced on d)
    {
        const int c = t & 63, p0 = t >> 6;
        #pragma unroll
        for (int p = p0; p < 32; p += 4) {
            Wu[p][c] = pack2(Wout[(2 * p) * 64 + c],      Wout[(2 * p + 1) * 64 + c]);
            Wv[p][c] = pack2(Wout[(64 + 2 * p) * 64 + c], Wout[(65 + 2 * p) * 64 + c]);
        }
    }
    __syncthreads();

    // Thread tile: 3 rows (stride-16) x 8 cols
    const int rt = t & 15;
    const int ct = t >> 4;            // ct<8 => u cols, ct>=8 => v cols
    const int ccol = (ct & 7) * 8;
    const bool isv = (ct >= 8);
    const u64 (*Ws)[64] = isv ? Wv : Wu;

    u64 acc[3][8];
    #pragma unroll
    for (int ii = 0; ii < 3; ii++)
        #pragma unroll
        for (int j = 0; j < 8; j++) acc[ii][j] = 0ull;

    #pragma unroll 8
    for (int p = 0; p < 32; p++) {
        u64 xv[3];
        #pragma unroll
        for (int ii = 0; ii < 3; ii++) xv[ii] = xs[p][rt + 16 * ii];
        u64 wv[8];
        #pragma unroll
        for (int q = 0; q < 4; q++) {
            ulonglong2 w2 = *(const ulonglong2*)&Ws[p][ccol + 2 * q];
            wv[2 * q] = w2.x; wv[2 * q + 1] = w2.y;
        }
        #pragma unroll
        for (int ii = 0; ii < 3; ii++)
            #pragma unroll
            for (int j = 0; j < 8; j++)
                ffma2(acc[ii][j], xv[ii], wv[j]);   // lo: even-k partial, hi: odd-k partial
    }

    // Epilogue: reduce lo+hi, add b_out for v-half, store transposed pairs
    u64* gdst = isv ? g_v2 : g_u2;
    #pragma unroll
    for (int ii = 0; ii < 3; ii++) {
        const int grow = row0 + rt + 16 * ii;     // [0, 5760)
        const int bb = grow / 360;
        const int i = grow - bb * 360;
        #pragma unroll
        for (int j = 0; j < 8; j += 2) {
            float l0, h0, l1, h1;
            unpack2(acc[ii][j], l0, h0);
            unpack2(acc[ii][j + 1], l1, h1);
            float v0 = l0 + h0, v1 = l1 + h1;
            const int dd = ccol + j;
            if (isv) { v0 += __ldg(&bout[dd]); v1 += __ldg(&bout[dd + 1]); }
            gdst[(bb * 32 + (dd >> 1)) * RPAD + i] = pack2(v0, v1);
        }
    }
}

// ============================================================================
// Kernel 2: out[b,rec,send] = relu( sum_d Wcat[d]*relu(u[send,d]+v[rec,d]) + b_cat )
// Tile: 64 rec x 64 send per block, 256 threads, 4x4 outputs/thread,
// fp32x2-packed over d-pairs. 64 regs -> 4 CTAs/SM -> 32 warps.
// ============================================================================
__global__ __launch_bounds__(256, 4) void k2_pair(
    const float* __restrict__ Wcat,   // [64]
    const float* __restrict__ bcat,   // [1]
    float* __restrict__ out)          // [16*360*360]
{
    __shared__ u64 Us[32][64];    // [dpair][send]
    __shared__ u64 Vs[32][64];    // [dpair][rec]
    __shared__ u64 Ww[32];        // packed Wcat pairs

    const int t = threadIdx.x;
    const int b  = blockIdx.z;
    const int s0 = blockIdx.x * 64;
    const int r0 = blockIdx.y * 64;

    // Fill tiles (coalesced 512B rows; pad region [360,384) holds zeros — harmless)
    {
        const int c = t & 63, k0 = t >> 6;
        const u64* gu = g_u2 + b * 32 * RPAD + s0 + c;
        const u64* gv = g_v2 + b * 32 * RPAD + r0 + c;
        #pragma unroll
        for (int k = k0; k < 32; k += 4) {
            Us[k][c] = gu[k * RPAD];
            Vs[k][c] = gv[k * RPAD];
        }
        if (t < 32) Ww[t] = ((const u64*)Wcat)[t];
    }
    __syncthreads();

    const int sx = (t & 15) * 4;   // send base
    const int ry = (t >> 4) * 4;   // rec base

    u64 acc[4][4];
    #pragma unroll
    for (int i = 0; i < 4; i++)
        #pragma unroll
        for (int j = 0; j < 4; j++) acc[i][j] = 0ull;

    #pragma unroll 4
    for (int k = 0; k < 32; k++) {
        const u64 w2 = Ww[k];   // LDS broadcast
        u64 uu[4];
        {
            ulonglong2 ua = *(const ulonglong2*)&Us[k][sx];
            ulonglong2 ub = *(const ulonglong2*)&Us[k][sx + 2];
            uu[0] = ua.x; uu[1] = ua.y; uu[2] = ub.x; uu[3] = ub.y;
        }
        u64 vv[4];
        {
            ulonglong2 va = *(const ulonglong2*)&Vs[k][ry];
            ulonglong2 vb = *(const ulonglong2*)&Vs[k][ry + 2];
            vv[0] = va.x; vv[1] = va.y; vv[2] = vb.x; vv[3] = vb.y;
        }
        #pragma unroll
        for (int i = 0; i < 4; i++)
            #pragma unroll
            for (int j = 0; j < 4; j++) {
                u64 tt = relu2(fadd2(uu[j], vv[i]));
                ffma2(acc[i][j], tt, w2);
            }
    }

    // Epilogue: lo+hi + b_cat, relu, float4 stores (guarded against the 360->384 pad)
    const float bc = __ldg(bcat);
    const int s = s0 + sx;
    if (s < R) {
        #pragma unroll
        for (int i = 0; i < 4; i++) {
            const int rec = r0 + ry + i;
            if (rec < R) {
                float4 o;
                float lx, hx;
                unpack2(acc[i][0], lx, hx); o.x = fmaxf(lx + hx + bc, 0.0f);
                unpack2(acc[i][1], lx, hx); o.y = fmaxf(lx + hx + bc, 0.0f);
                unpack2(acc[i][2], lx, hx); o.z = fmaxf(lx + hx + bc, 0.0f);
                unpack2(acc[i][3], lx, hx); o.w = fmaxf(lx + hx + bc, 0.0f);
                *(float4*)&out[((size_t)(b * R + rec)) * R + s] = o;
            }
        }
    }
}

extern "C" void kernel_launch(void* const* d_in, const int* in_sizes, int n_in,
                              void* d_out, int out_size) {
    (void)in_sizes; (void)n_in; (void)out_size;
    const float* x    = (const float*)d_in[0];  // (16,360,64)
    const float* Wout = (const float*)d_in[1];  // (128,64)
    const float* bout = (const float*)d_in[2];  // (64)
    const float* Wcat = (const float*)d_in[3];  // (64,1)
    const float* bcat = (const float*)d_in[4];  // (1)
    float* out = (float*)d_out;                 // (16,360,360,1) fp32

    k1_uv<<<120, 256>>>(x, Wout, bout);                   // 5760 rows / 48
    k2_pair<<<dim3(6, 6, 16), 256>>>(Wcat, bcat, out);    // 6 send x 6 rec x 16 batch
}